// round 13
// baseline (speedup 1.0000x reference)
#include <cuda_runtime.h>
#include <cstddef>
#include <cstdint>

#define MM 1536
#define BLOCKS 8           /* one cluster */
#define WPB 6
#define STRIPS 48          /* BLOCKS * WPB */
#define TEND 1568          /* >= MM + 31, multiple of 8 */
#define TALLOC 1600
#define SBCOLS 1552        /* boundary columns (>= MM+1), 16B quads */

#define L2E  1.4426950408889634f
#define LN2  0.6931471805599453f
#define NEGB (-1.0e8f * L2E)

// Pre-skewed, padded theta: g_th3[((s*TALLOC + t)*3 + q)*128 + lane*4 + j]
__device__ float g_th3[(size_t)STRIPS * TALLOC * 384];

// ---- smem/DSMEM access helpers ----
__device__ __forceinline__ uint32_t mapa_cluster(uint32_t saddr, uint32_t rank) {
    uint32_t r;
    asm("mapa.shared::cluster.u32 %0, %1, %2;" : "=r"(r) : "r"(saddr), "r"(rank));
    return r;
}
__device__ __forceinline__ float4 ldv4_s(uint32_t a) {        // local smem, tear-free 128b
    float4 v;
    asm volatile("ld.volatile.shared.v4.f32 {%0,%1,%2,%3}, [%4];"
                 : "=f"(v.x), "=f"(v.y), "=f"(v.z), "=f"(v.w) : "r"(a) : "memory");
    return v;
}
__device__ __forceinline__ float4 ldv4_c(uint32_t a) {        // remote (DSMEM) 128b
    float4 v;
    asm volatile("ld.volatile.shared::cluster.v4.f32 {%0,%1,%2,%3}, [%4];"
                 : "=f"(v.x), "=f"(v.y), "=f"(v.z), "=f"(v.w) : "r"(a) : "memory");
    return v;
}
__device__ __forceinline__ void stv4_s(uint32_t a, float4 v) { // local smem store 128b
    asm volatile("st.volatile.shared.v4.f32 [%0], {%1,%2,%3,%4};"
                 :: "r"(a), "f"(v.x), "f"(v.y), "f"(v.z), "f"(v.w) : "memory");
}
__device__ __forceinline__ void nsleep(unsigned ns) {
    asm volatile("nanosleep.u32 %0;" :: "r"(ns));
}

__device__ __forceinline__ float ex2_(float x) {
    float y; asm("ex2.approx.ftz.f32 %0, %1;" : "=f"(y) : "f"(x)); return y;
}
__device__ __forceinline__ float lg2_(float x) {
    float y; asm("lg2.approx.ftz.f32 %0, %1;" : "=f"(y) : "f"(x)); return y;
}
__device__ __forceinline__ float lse3_(float a, float b, float c) {
    float hi = fmaxf(a, b), lo = fminf(a, b);
    float m  = fmaxf(hi, c), s2 = fminf(hi, c);
    return m + lg2_(1.0f + ex2_(lo - m) + ex2_(s2 - m));
}

// ---------------- transpose: theta -> padded skewed layout (unchanged) ------
#define TT 32
#define RG 8
#define NCOL (TT + RG - 1)
#define SROW (NCOL * 9)

__global__ void __launch_bounds__(256)
hmm_transpose_kernel(const float* __restrict__ theta)
{
    __shared__ float s[RG][SROW];
    const int g   = blockIdx.x;
    const int T0  = blockIdx.y * TT;
    const int r0  = blockIdx.z * RG;
    const int tid = threadIdx.x;
    const long NTOT = (long)MM * MM * 9;
    const int C0  = T0 - r0 - (RG - 1);

    #pragma unroll
    for (int row = 0; row < RG; row++) {
        long base = (long)(32 * g + r0 + row) * (MM * 9) + (long)C0 * 9;
        for (int i = tid; i < SROW; i += 256) {
            long idx = base + i;
            idx = idx < 0 ? 0 : (idx >= NTOT ? NTOT - 1 : idx);
            s[row][i] = theta[idx] * L2E;
        }
    }
    __syncthreads();

    float* outb = g_th3 + ((size_t)g * TALLOC + T0) * 384 + r0 * 4;
    #pragma unroll
    for (int k = 0; k < 12; k++) {
        int flat = tid + k * 256;
        int j    = flat & 3;
        int row  = (flat >> 2) & 7;
        int rest = flat >> 5;
        int q    = rest % 3;
        int t_i  = rest / 3;
        int e    = q * 4 + j;
        float v  = 0.0f;
        if (e < 9) v = s[row][(t_i - row + 7) * 9 + e];
        outb[(size_t)t_i * 384 + q * 128 + row * 4 + j] = v;
    }
}

// ---- wavefront DP: cluster of 8 blocks x 6 warps; producers get HIGHER wid -
__global__ void __launch_bounds__(192, 1) __cluster_dims__(BLOCKS, 1, 1)
hmm_fwd_kernel(float* __restrict__ out)
{
    extern __shared__ float4 smb[];   // [WPB][SBCOLS]; row w = warp w's boundary output
    const int b   = blockIdx.x;
    const int w   = threadIdx.x >> 5;
    const int r   = threadIdx.x & 31;
    const int tid = threadIdx.x;

    // zero validity each launch
    for (int i = tid; i < WPB * SBCOLS; i += 192)
        smb[i] = make_float4(0.f, 0.f, 0.f, 0.f);

    asm volatile("barrier.cluster.arrive.aligned;" ::: "memory");
    asm volatile("barrier.cluster.wait.aligned;" ::: "memory");

    // REVERSED map: higher wid = earlier strip = producer side of the arbiter.
    const int s = b * WPB + (WPB - 1 - w);
    const float4* tb4 = (const float4*)g_th3 + (size_t)s * TALLOC * 96 + r;

    const bool consS   = (w < WPB - 1);                  // consume warp w+1's row (local)
    const bool consC   = (w == WPB - 1) && (b > 0);      // consume block b-1 warp 0's row (DSMEM)
    const bool lane0c  = (r == 0) && (consS || consC);
    const bool prod31  = (r == 31) && (s < STRIPS - 1);

    uint32_t pS = (uint32_t)__cvta_generic_to_shared(smb + (size_t)w * SBCOLS);
    uint32_t cS;
    if (consC) {
        uint32_t row0 = (uint32_t)__cvta_generic_to_shared(smb);   // row of warp 0
        cS = mapa_cluster(row0, (uint32_t)(b - 1));
    } else {
        cS = (uint32_t)__cvta_generic_to_shared(smb + (size_t)(consS ? (w + 1) : 0) * SBCOLS);
    }

    float vM = NEGB, vX = NEGB, vY = NEGB;
    float duM, duX, duY;
    duM = duX = duY = (s == 0 && r == 0) ? 0.0f : NEGB;   // V(0,0) = 0

    float4 bq[8], spec[8];
    #pragma unroll
    for (int q = 0; q < 8; q++) {
        bq[q] = make_float4(NEGB, NEGB, NEGB, 1.0f);
        spec[q] = bq[q];
    }

    float4 thA[4][3], thB[4][3];
    auto loadGroup = [&](int tbase, float4 (&dst)[4][3]) {
        #pragma unroll
        for (int q = 0; q < 4; q++) {
            const float4* p = tb4 + (size_t)(tbase + q) * 96;
            dst[q][0] = __ldg(p);
            dst[q][1] = __ldg(p + 32);
            dst[q][2] = __ldg(p + 64);
        }
    };

    // gentle poll: sleeps (leaves the arbiter's eligible set) instead of hot-spinning
    auto pollQuad = [&](int c) -> float4 {
        uint32_t a = cS + (uint32_t)c * 16;
        float4 v = consC ? ldv4_c(a) : ldv4_s(a);
        unsigned ns = 40;
        while (v.w == 0.0f) {
            nsleep(ns);
            if (ns < 800) ns <<= 1;
            v = consC ? ldv4_c(a) : ldv4_s(a);
        }
        return v;
    };

    auto step = [&](int t, const float4 (&th)[3], float4 bb) {
        float nuM = __shfl_up_sync(0xffffffffu, vM, 1);
        float nuX = __shfl_up_sync(0xffffffffu, vX, 1);
        float nuY = __shfl_up_sync(0xffffffffu, vY, 1);
        if (r == 0) { nuM = bb.x; nuX = bb.y; nuY = bb.z; }
        int col = t - r;
        if ((unsigned)col < (unsigned)MM) {
            float a  = lse3_(duM + th[0].x, duX + th[0].y, duY + th[0].z); // M <- diag
            float b2 = lse3_(nuM + th[0].w, nuX + th[1].x, nuY + th[1].y); // X <- up
            float c  = lse3_(vM  + th[1].z, vX  + th[1].w, vY  + th[2].x); // Y <- left
            vM = a; vX = b2; vY = c;
            if (prod31) {
                int j = col + 1;
                stv4_s(pS + (uint32_t)j * 16, make_float4(a, b2, c, 1.0f));
            }
        }
        duM = nuM; duX = nuX; duY = nuY;
    };

    auto loadSpec = [&](int t0) {   // speculative prefetch of next chunk's boundary
        #pragma unroll
        for (int q = 0; q < 8; q++) {
            int c = t0 + 9 + q; if (c > MM) c = MM;
            uint32_t a = cS + (uint32_t)c * 16;
            spec[q] = consC ? ldv4_c(a) : ldv4_s(a);
        }
    };

    // ---- prologue ----
    loadGroup(0, thA);
    loadGroup(4, thB);
    if (lane0c) {
        #pragma unroll
        for (int q = 0; q < 8; q++) bq[q] = pollQuad(1 + q);
    }

    // ---- main loop ----
    for (int t0 = 0; t0 < TEND; t0 += 8) {
        if (lane0c && t0 < MM) loadSpec(t0);   // issue early; validate at chunk end

        step(t0 + 0, thA[0], bq[0]);
        step(t0 + 1, thA[1], bq[1]);
        step(t0 + 2, thA[2], bq[2]);
        step(t0 + 3, thA[3], bq[3]);
        loadGroup(t0 + 8, thA);
        step(t0 + 4, thB[0], bq[4]);
        step(t0 + 5, thB[1], bq[5]);
        step(t0 + 6, thB[2], bq[6]);
        step(t0 + 7, thB[3], bq[7]);
        loadGroup(t0 + 12, thB);

        if (lane0c && t0 < MM) {
            bool ok = true;
            #pragma unroll
            for (int q = 0; q < 8; q++) ok = ok && (spec[q].w != 0.0f);
            if (ok) {
                #pragma unroll
                for (int q = 0; q < 8; q++) bq[q] = spec[q];
            } else {
                #pragma unroll
                for (int q = 0; q < 8; q++) {
                    int c = t0 + 9 + q; if (c > MM) c = MM;
                    bq[q] = pollQuad(c);       // gentle catch-up
                }
            }
        }
    }

    if (s == STRIPS - 1 && r == 31) {
        out[0] = LN2 * lse3_(vM, vX, vY);
    }

    // keep smem alive until every block is done reading peers
    asm volatile("barrier.cluster.arrive.aligned;" ::: "memory");
    asm volatile("barrier.cluster.wait.aligned;" ::: "memory");
}

extern "C" void kernel_launch(void* const* d_in, const int* in_sizes, int n_in,
                              void* d_out, int out_size)
{
    const float* theta = (const float*)d_in[0];
    float* out = (float*)d_out;

    const size_t smemBytes = (size_t)WPB * SBCOLS * sizeof(float4);  // 148,992 B
    cudaFuncSetAttribute(hmm_fwd_kernel,
                         cudaFuncAttributeMaxDynamicSharedMemorySize,
                         (int)smemBytes);

    dim3 tgrid(STRIPS, TALLOC / TT, 32 / RG);
    hmm_transpose_kernel<<<tgrid, 256>>>(theta);
    hmm_fwd_kernel<<<BLOCKS, WPB * 32, smemBytes>>>(out);
}

// round 14
// speedup vs baseline: 1.0701x; 1.0701x over previous
#include <cuda_runtime.h>
#include <cuda_fp16.h>
#include <cstddef>
#include <cstdint>

#define MM 1536
#define BLOCKS 12
#define WPB 4
#define STRIPS 48          /* BLOCKS * WPB */
#define TEND 1568          /* >= MM + 31, multiple of 8 */
#define TALLOC 1600
#define SBCOLS 1552        /* boundary columns (>= MM+1), 16B quads */

#define L2E  1.4426950408889634f
#define LN2  0.6931471805599453f
#define NEGB (-1.0e8f * L2E)

// Pre-skewed, padded theta: g_th3[((s*TALLOC + t)*3 + q)*128 + lane*4 + j]
__device__ float g_th3[(size_t)STRIPS * TALLOC * 384];

// Inter-block boundary: one float4 {M, X, Y, valid} per column.
__device__ float4 g_b4[BLOCKS][SBCOLS];

__global__ void hmm_init_kernel() {
    int i = blockIdx.x * blockDim.x + threadIdx.x;
    if (i < BLOCKS * SBCOLS)
        ((float4*)g_b4)[i] = make_float4(0.f, 0.f, 0.f, 0.f);
}

// ---- tear-free 128-bit volatile loads ----
__device__ __forceinline__ float4 ldv4_g(const float4* p) {
    float4 v;
    asm volatile("ld.volatile.global.v4.f32 {%0,%1,%2,%3}, [%4];"
                 : "=f"(v.x), "=f"(v.y), "=f"(v.z), "=f"(v.w) : "l"(p) : "memory");
    return v;
}
__device__ __forceinline__ float4 ldv4_s(uint32_t a) {
    float4 v;
    asm volatile("ld.volatile.shared.v4.f32 {%0,%1,%2,%3}, [%4];"
                 : "=f"(v.x), "=f"(v.y), "=f"(v.z), "=f"(v.w) : "r"(a) : "memory");
    return v;
}

__device__ __forceinline__ float ex2_(float x) {
    float y; asm("ex2.approx.ftz.f32 %0, %1;" : "=f"(y) : "f"(x)); return y;
}
__device__ __forceinline__ float lg2_(float x) {
    float y; asm("lg2.approx.ftz.f32 %0, %1;" : "=f"(y) : "f"(x)); return y;
}
// f32 lse3 (used on the Y critical chain and in guarded ramp/tail steps)
__device__ __forceinline__ float lse3_(float a, float b, float c) {
    float hi = fmaxf(a, b), lo = fminf(a, b);
    float m  = fmaxf(hi, c), s2 = fminf(hi, c);
    return m + lg2_(1.0f + ex2_(lo - m) + ex2_(s2 - m));
}
// f32 lse2
__device__ __forceinline__ float lse2_(float a, float b) {
    float m = fmaxf(a, b), d = fminf(a, b) - m;
    return m + lg2_(1.0f + ex2_(d));
}
// lse3 with both ex2 packed into one ex2.approx.f16x2 (off-chain M/X states only)
__device__ __forceinline__ float lse3h_(float a, float b, float c) {
    float hi = fmaxf(a, b), lo = fminf(a, b);
    float m  = fmaxf(hi, c), s2 = fminf(hi, c);
    __half2 hd = __floats2half2_rn(lo - m, s2 - m);   // diffs <= 0, -inf ok
    __half2 he = h2exp2(hd);
    float e = __low2float(he) + __high2float(he);
    return m + lg2_(1.0f + e);
}

// ---------------- transpose: theta -> padded skewed layout (unchanged) ------
#define TT 32
#define RG 8
#define NCOL (TT + RG - 1)
#define SROW (NCOL * 9)

__global__ void __launch_bounds__(256)
hmm_transpose_kernel(const float* __restrict__ theta)
{
    __shared__ float s[RG][SROW];
    const int g   = blockIdx.x;
    const int T0  = blockIdx.y * TT;
    const int r0  = blockIdx.z * RG;
    const int tid = threadIdx.x;
    const long NTOT = (long)MM * MM * 9;
    const int C0  = T0 - r0 - (RG - 1);

    #pragma unroll
    for (int row = 0; row < RG; row++) {
        long base = (long)(32 * g + r0 + row) * (MM * 9) + (long)C0 * 9;
        for (int i = tid; i < SROW; i += 256) {
            long idx = base + i;
            idx = idx < 0 ? 0 : (idx >= NTOT ? NTOT - 1 : idx);
            s[row][i] = theta[idx] * L2E;
        }
    }
    __syncthreads();

    float* outb = g_th3 + ((size_t)g * TALLOC + T0) * 384 + r0 * 4;
    #pragma unroll
    for (int k = 0; k < 12; k++) {
        int flat = tid + k * 256;
        int j    = flat & 3;
        int row  = (flat >> 2) & 7;
        int rest = flat >> 5;
        int q    = rest % 3;
        int t_i  = rest / 3;
        int e    = q * 4 + j;
        float v  = 0.0f;
        if (e < 9) v = s[row][(t_i - row + 7) * 9 + e];
        outb[(size_t)t_i * 384 + q * 128 + row * 4 + j] = v;
    }
}

// ---------------- wavefront DP: 12 blocks x 4 warps, 2-step Y-jump ----------
__global__ void __launch_bounds__(128, 1)
hmm_fwd_kernel(float* __restrict__ out)
{
    extern __shared__ float4 smb[];   // [WPB-1][SBCOLS]
    const int b   = blockIdx.x;
    const int wid = threadIdx.x >> 5;
    const int r   = threadIdx.x & 31;
    const int tid = threadIdx.x;

    for (int i = tid; i < (WPB - 1) * SBCOLS; i += 128)
        smb[i] = make_float4(0.f, 0.f, 0.f, 0.f);
    __syncthreads();

    const int s = b * WPB + wid;
    const float4* tb4 = (const float4*)g_th3 + (size_t)s * TALLOC * 96 + r;

    const bool consS   = (wid > 0);
    const bool consG   = (wid == 0 && b > 0);
    const bool lane0c  = (r == 0) && (consS || consG);
    const bool prodS31 = (r == 31) && (wid < WPB - 1);
    const bool prodG31 = (r == 31) && (wid == WPB - 1) && (b < BLOCKS - 1);

    float4* pS = smb + (prodS31 ? wid : 0) * SBCOLS;
    uint32_t cS = (uint32_t)__cvta_generic_to_shared(
                      smb + (consS ? (wid - 1) : 0) * SBCOLS);
    const float4* cG = &g_b4[(b > 0) ? (b - 1) : 0][0];
    float4* pG = &g_b4[b][0];

    float vM = NEGB, vX = NEGB, vY = NEGB;
    float duM, duX, duY;
    duM = duX = duY = (s == 0 && r == 0) ? 0.0f : NEGB;

    float4 bq[8], spec[8];
    #pragma unroll
    for (int q = 0; q < 8; q++) {
        bq[q] = make_float4(NEGB, NEGB, NEGB, 1.0f);
        spec[q] = bq[q];
    }

    float4 thA[4][3], thB[4][3];
    auto loadGroup = [&](int tbase, float4 (&dst)[4][3]) {
        #pragma unroll
        for (int q = 0; q < 4; q++) {
            const float4* p = tb4 + (size_t)(tbase + q) * 96;
            dst[q][0] = __ldg(p);
            dst[q][1] = __ldg(p + 32);
            dst[q][2] = __ldg(p + 64);
        }
    };

    // guarded per-step update (ramp/tail)
    auto step = [&](int t, const float4 (&th)[3], float4 bb) {
        float nuM = __shfl_up_sync(0xffffffffu, vM, 1);
        float nuX = __shfl_up_sync(0xffffffffu, vX, 1);
        float nuY = __shfl_up_sync(0xffffffffu, vY, 1);
        if (r == 0) { nuM = bb.x; nuX = bb.y; nuY = bb.z; }
        int col = t - r;
        if ((unsigned)col < (unsigned)MM) {
            float a  = lse3_(duM + th[0].x, duX + th[0].y, duY + th[0].z);
            float b2 = lse3_(nuM + th[0].w, nuX + th[1].x, nuY + th[1].y);
            float c  = lse3_(vM  + th[1].z, vX  + th[1].w, vY  + th[2].x);
            vM = a; vX = b2; vY = c;
            int j = col + 1;
            float4 o = make_float4(a, b2, c, 1.0f);
            if (prodS31) pS[j] = o;
            if (prodG31) pG[j] = o;
        }
        duM = nuM; duX = nuX; duY = nuY;
    };

    // fast pair: steps (t, t+1), ALL lanes active. Chain: vY -> c2 only.
    auto pairstep = [&](int t, const float4 (&thE)[3], const float4 (&thO)[3],
                        float4 bbE, float4 bbO) {
        // step E shuffles
        float nuM = __shfl_up_sync(0xffffffffu, vM, 1);
        float nuX = __shfl_up_sync(0xffffffffu, vX, 1);
        float nuY = __shfl_up_sync(0xffffffffu, vY, 1);
        if (r == 0) { nuM = bbE.x; nuX = bbE.y; nuY = bbE.z; }
        float zE = vY + thE[2].x;                        // c(t-1)+th8(t)  [chain]
        float a1 = lse3h_(duM + thE[0].x, duX + thE[0].y, duY + thE[0].z);
        float b1 = lse3h_(nuM + thE[0].w, nuX + thE[1].x, nuY + thE[1].y);
        float w1 = lse2_(vM + thE[1].z, vX + thE[1].w);  // off-chain
        float c1 = lse2_(w1, zE);                        // c(t) (for shfl/store)
        // step O shuffles (carry E results)
        float nuM2 = __shfl_up_sync(0xffffffffu, a1, 1);
        float nuX2 = __shfl_up_sync(0xffffffffu, b1, 1);
        float nuY2 = __shfl_up_sync(0xffffffffu, c1, 1);
        if (r == 0) { nuM2 = bbO.x; nuX2 = bbO.y; nuY2 = bbO.z; }
        float a2 = lse3h_(nuM + thO[0].x, nuX + thO[0].y, nuY + thO[0].z);   // du(O)=nu(E)
        float b2 = lse3h_(nuM2 + thO[0].w, nuX2 + thO[1].x, nuY2 + thO[1].y);
        float w2 = lse2_(a1 + thO[1].z, b1 + thO[1].w);
        // c(t+1) = lse3(w2, w1+th8(t+1), c(t-1)+th8(t)+th8(t+1)) — 2-step jump
        float c2 = lse3_(w2, w1 + thO[2].x, zE + thO[2].x);
        if (prodS31 | prodG31) {
            int j = t - 30;                              // colE+1 for lane 31
            float4 o1 = make_float4(a1, b1, c1, 1.0f);
            float4 o2 = make_float4(a2, b2, c2, 1.0f);
            if (prodS31) { pS[j] = o1; pS[j + 1] = o2; }
            if (prodG31) { pG[j] = o1; pG[j + 1] = o2; }
        }
        vM = a2; vX = b2; vY = c2;
        duM = nuM2; duX = nuX2; duY = nuY2;
    };

    auto loadSpec = [&](int t0) {
        #pragma unroll
        for (int q = 0; q < 8; q++) {
            int c = t0 + 9 + q; if (c > MM) c = MM;
            spec[q] = consS ? ldv4_s(cS + (uint32_t)c * 16) : ldv4_g(cG + c);
        }
    };
    auto validate = [&](int t0) {
        bool ok = true;
        #pragma unroll
        for (int q = 0; q < 8; q++) ok = ok && (spec[q].w != 0.0f);
        while (!ok) {
            loadSpec(t0);
            ok = true;
            #pragma unroll
            for (int q = 0; q < 8; q++) ok = ok && (spec[q].w != 0.0f);
        }
        #pragma unroll
        for (int q = 0; q < 8; q++) bq[q] = spec[q];
    };

    // ---- prologue ----
    loadGroup(0, thA);
    loadGroup(4, thB);
    if (lane0c) {
        bool ok;
        do {
            #pragma unroll
            for (int q = 0; q < 8; q++)
                bq[q] = consS ? ldv4_s(cS + (uint32_t)(1 + q) * 16) : ldv4_g(cG + 1 + q);
            ok = true;
            #pragma unroll
            for (int q = 0; q < 8; q++) ok = ok && (bq[q].w != 0.0f);
        } while (!ok);
    }

    // ---- ramp: t0 = 0..24 (guarded steps) ----
    for (int t0 = 0; t0 < 32; t0 += 8) {
        if (lane0c) loadSpec(t0);
        step(t0 + 0, thA[0], bq[0]);
        step(t0 + 1, thA[1], bq[1]);
        step(t0 + 2, thA[2], bq[2]);
        step(t0 + 3, thA[3], bq[3]);
        loadGroup(t0 + 8, thA);
        step(t0 + 4, thB[0], bq[4]);
        step(t0 + 5, thB[1], bq[5]);
        step(t0 + 6, thB[2], bq[6]);
        step(t0 + 7, thB[3], bq[7]);
        loadGroup(t0 + 12, thB);
        if (lane0c) validate(t0);
    }

    // ---- fast: t0 = 32..1528 (pairs, all lanes active) ----
    for (int t0 = 32; t0 < 1536; t0 += 8) {
        if (lane0c) loadSpec(t0);
        pairstep(t0 + 0, thA[0], thA[1], bq[0], bq[1]);
        pairstep(t0 + 2, thA[2], thA[3], bq[2], bq[3]);
        loadGroup(t0 + 8, thA);
        pairstep(t0 + 4, thB[0], thB[1], bq[4], bq[5]);
        pairstep(t0 + 6, thB[2], thB[3], bq[6], bq[7]);
        loadGroup(t0 + 12, thB);
        if (lane0c) validate(t0);
    }

    // ---- tail: t0 = 1536..1560 (guarded; lane 0 boundary exhausted) ----
    for (int t0 = 1536; t0 < TEND; t0 += 8) {
        step(t0 + 0, thA[0], bq[0]);
        step(t0 + 1, thA[1], bq[1]);
        step(t0 + 2, thA[2], bq[2]);
        step(t0 + 3, thA[3], bq[3]);
        loadGroup(t0 + 8, thA);
        step(t0 + 4, thB[0], bq[4]);
        step(t0 + 5, thB[1], bq[5]);
        step(t0 + 6, thB[2], bq[6]);
        step(t0 + 7, thB[3], bq[7]);
        loadGroup(t0 + 12, thB);
    }

    if (s == STRIPS - 1 && r == 31) {
        out[0] = LN2 * lse3_(vM, vX, vY);
    }
}

extern "C" void kernel_launch(void* const* d_in, const int* in_sizes, int n_in,
                              void* d_out, int out_size)
{
    const float* theta = (const float*)d_in[0];
    float* out = (float*)d_out;

    const size_t smemBytes = (size_t)(WPB - 1) * SBCOLS * sizeof(float4);
    cudaFuncSetAttribute(hmm_fwd_kernel,
                         cudaFuncAttributeMaxDynamicSharedMemorySize,
                         (int)smemBytes);

    dim3 tgrid(STRIPS, TALLOC / TT, 32 / RG);
    hmm_transpose_kernel<<<tgrid, 256>>>(theta);
    hmm_init_kernel<<<(BLOCKS * SBCOLS + 255) / 256, 256>>>();
    hmm_fwd_kernel<<<BLOCKS, WPB * 32, smemBytes>>>(out);
}

// round 15
// speedup vs baseline: 2.1154x; 1.9769x over previous
#include <cuda_runtime.h>
#include <cuda_fp16.h>
#include <cstddef>
#include <cstdint>

#define MM 1536
#define BLOCKS 12
#define WPB 4
#define STRIPS 48            /* BLOCKS * WPB */
#define TEND 1568            /* steps per strip, multiple of 16 */
#define TALLOC 1600
#define NSUP (TEND / 16)     /* 98 active supersteps per strip */
#define LAGS 3               /* superstep lag between adjacent strips (48 steps) */
#define KTOT (LAGS * (STRIPS - 1) + NSUP)   /* 239 */

#define L2E  1.4426950408889634f
#define LN2  0.6931471805599453f
#define NEGB (-1.0e8f * L2E)

// Pre-skewed, padded theta: g_th3[((s*TALLOC + t)*3 + q)*128 + lane*4 + j]
__device__ float g_th3[(size_t)STRIPS * TALLOC * 384];

// Cross-block rolling boundary windows (64 cols each) + barrier state
__device__ float4   g_win[BLOCKS][64];
__device__ unsigned g_bar_count;
__device__ unsigned g_bar_phase;

__global__ void hmm_init_kernel() {
    if (threadIdx.x == 0) { g_bar_count = 0; g_bar_phase = 0; }
}

__device__ __forceinline__ unsigned ld_acq_u(const unsigned* p) {
    unsigned v;
    asm volatile("ld.acquire.gpu.global.u32 %0, [%1];" : "=r"(v) : "l"(p) : "memory");
    return v;
}
__device__ __forceinline__ float4 ldv4_g(const float4* p) {
    float4 v;
    asm volatile("ld.volatile.global.v4.f32 {%0,%1,%2,%3}, [%4];"
                 : "=f"(v.x), "=f"(v.y), "=f"(v.z), "=f"(v.w) : "l"(p) : "memory");
    return v;
}
__device__ __forceinline__ void nsleep(unsigned ns) {
    asm volatile("nanosleep.u32 %0;" :: "r"(ns));
}

__device__ __forceinline__ float ex2_(float x) {
    float y; asm("ex2.approx.ftz.f32 %0, %1;" : "=f"(y) : "f"(x)); return y;
}
__device__ __forceinline__ float lg2_(float x) {
    float y; asm("lg2.approx.ftz.f32 %0, %1;" : "=f"(y) : "f"(x)); return y;
}
__device__ __forceinline__ float lse3_(float a, float b, float c) {
    float hi = fmaxf(a, b), lo = fminf(a, b);
    float m  = fmaxf(hi, c), s2 = fminf(hi, c);
    return m + lg2_(1.0f + ex2_(lo - m) + ex2_(s2 - m));
}
__device__ __forceinline__ float lse2_(float a, float b) {
    float m = fmaxf(a, b), d = fminf(a, b) - m;
    return m + lg2_(1.0f + ex2_(d));
}
__device__ __forceinline__ float lse3h_(float a, float b, float c) {
    float hi = fmaxf(a, b), lo = fminf(a, b);
    float m  = fmaxf(hi, c), s2 = fminf(hi, c);
    __half2 hd = __floats2half2_rn(lo - m, s2 - m);
    __half2 he = h2exp2(hd);
    float e = __low2float(he) + __high2float(he);
    return m + lg2_(1.0f + e);
}

// ---------------- transpose: theta -> padded skewed layout (unchanged) ------
#define TT 32
#define RG 8
#define NCOL (TT + RG - 1)
#define SROW (NCOL * 9)

__global__ void __launch_bounds__(256)
hmm_transpose_kernel(const float* __restrict__ theta)
{
    __shared__ float s[RG][SROW];
    const int g   = blockIdx.x;
    const int T0  = blockIdx.y * TT;
    const int r0  = blockIdx.z * RG;
    const int tid = threadIdx.x;
    const long NTOT = (long)MM * MM * 9;
    const int C0  = T0 - r0 - (RG - 1);

    #pragma unroll
    for (int row = 0; row < RG; row++) {
        long base = (long)(32 * g + r0 + row) * (MM * 9) + (long)C0 * 9;
        for (int i = tid; i < SROW; i += 256) {
            long idx = base + i;
            idx = idx < 0 ? 0 : (idx >= NTOT ? NTOT - 1 : idx);
            s[row][i] = theta[idx] * L2E;
        }
    }
    __syncthreads();

    float* outb = g_th3 + ((size_t)g * TALLOC + T0) * 384 + r0 * 4;
    #pragma unroll
    for (int k = 0; k < 12; k++) {
        int flat = tid + k * 256;
        int j    = flat & 3;
        int row  = (flat >> 2) & 7;
        int rest = flat >> 5;
        int q    = rest % 3;
        int t_i  = rest / 3;
        int e    = q * 4 + j;
        float v  = 0.0f;
        if (e < 9) v = s[row][(t_i - row + 7) * 9 + e];
        outb[(size_t)t_i * 384 + q * 128 + row * 4 + j] = v;
    }
}

// -------- wavefront DP: static schedule + global barrier every 16 steps -----
__global__ void __launch_bounds__(128, 1)
hmm_fwd_kernel(float* __restrict__ out)
{
    __shared__ float4 swin[WPB][64];     // input window of each warp
    const int b   = blockIdx.x;
    const int wid = threadIdx.x >> 5;
    const int r   = threadIdx.x & 31;
    const int tid = threadIdx.x;

    for (int i = tid; i < WPB * 64; i += 128)
        ((float4*)swin)[i] = make_float4(NEGB, NEGB, NEGB, 1.0f);
    __syncthreads();

    const int s  = b * WPB + wid;        // global strip
    const int k0 = LAGS * s;             // first active superstep
    const float4* tb4 = (const float4*)g_th3 + (size_t)s * TALLOC * 96 + r;

    const bool consG = (wid == 0 && b > 0);         // cross-block consumer
    const bool prodS = (r == 31) && (wid < WPB - 1);
    const bool prodG = (r == 31) && (wid == WPB - 1) && (b < BLOCKS - 1);
    float4* sout = &swin[(wid < WPB - 1) ? (wid + 1) : 0][0];
    float4* gout = &g_win[b][0];
    const float4* gin = &g_win[(b > 0) ? (b - 1) : 0][0];
    const float4* sin_ = &swin[wid][0];

    float vM = NEGB, vX = NEGB, vY = NEGB;
    float duM, duX, duY;
    duM = duX = duY = (s == 0 && r == 0) ? 0.0f : NEGB;   // V(0,0)=0

    float4 bq[8];
    #pragma unroll
    for (int q = 0; q < 8; q++) bq[q] = make_float4(NEGB, NEGB, NEGB, 1.0f);

    float4 thA[4][3], thB[4][3];
    auto loadGroup = [&](int tbase, float4 (&dst)[4][3]) {
        #pragma unroll
        for (int q = 0; q < 4; q++) {
            const float4* p = tb4 + (size_t)(tbase + q) * 96;
            dst[q][0] = __ldg(p);
            dst[q][1] = __ldg(p + 32);
            dst[q][2] = __ldg(p + 64);
        }
    };

    auto loadBQ = [&](int c0) {          // DP cols c0..c0+7 from window slots
        #pragma unroll
        for (int q = 0; q < 8; q++) {
            int sl = (c0 + q) & 63;
            bq[q] = consG ? ldv4_g(gin + sl) : sin_[sl];
        }
    };

    auto emit = [&](int j, float4 o) {   // producer lane 31 writes DP col j
        if (prodS) sout[j & 63] = o;
        if (prodG) gout[j & 63] = o;
    };

    // guarded per-step update (ramp/tail supersteps)
    auto step = [&](int t, const float4 (&th)[3], float4 bb) {
        float nuM = __shfl_up_sync(0xffffffffu, vM, 1);
        float nuX = __shfl_up_sync(0xffffffffu, vX, 1);
        float nuY = __shfl_up_sync(0xffffffffu, vY, 1);
        if (r == 0) { nuM = bb.x; nuX = bb.y; nuY = bb.z; }
        int col = t - r;
        if ((unsigned)col < (unsigned)MM) {
            float a  = lse3_(duM + th[0].x, duX + th[0].y, duY + th[0].z);
            float b2 = lse3_(nuM + th[0].w, nuX + th[1].x, nuY + th[1].y);
            float c  = lse3_(vM  + th[1].z, vX  + th[1].w, vY  + th[2].x);
            vM = a; vX = b2; vY = c;
            emit(col + 1, make_float4(a, b2, c, 1.0f));
        }
        duM = nuM; duX = nuX; duY = nuY;
    };

    // fast pair (steps t, t+1; all lanes interior). Chain: vY -> c2 only.
    auto pairstep = [&](int t, const float4 (&thE)[3], const float4 (&thO)[3],
                        float4 bbE, float4 bbO) {
        float nuM = __shfl_up_sync(0xffffffffu, vM, 1);
        float nuX = __shfl_up_sync(0xffffffffu, vX, 1);
        float nuY = __shfl_up_sync(0xffffffffu, vY, 1);
        if (r == 0) { nuM = bbE.x; nuX = bbE.y; nuY = bbE.z; }
        float zE = vY + thE[2].x;
        float a1 = lse3h_(duM + thE[0].x, duX + thE[0].y, duY + thE[0].z);
        float b1 = lse3h_(nuM + thE[0].w, nuX + thE[1].x, nuY + thE[1].y);
        float w1 = lse2_(vM + thE[1].z, vX + thE[1].w);
        float c1 = lse2_(w1, zE);
        float nuM2 = __shfl_up_sync(0xffffffffu, a1, 1);
        float nuX2 = __shfl_up_sync(0xffffffffu, b1, 1);
        float nuY2 = __shfl_up_sync(0xffffffffu, c1, 1);
        if (r == 0) { nuM2 = bbO.x; nuX2 = bbO.y; nuY2 = bbO.z; }
        float a2 = lse3h_(nuM + thO[0].x, nuX + thO[0].y, nuY + thO[0].z);
        float b2 = lse3h_(nuM2 + thO[0].w, nuX2 + thO[1].x, nuY2 + thO[1].y);
        float w2 = lse2_(a1 + thO[1].z, b1 + thO[1].w);
        float c2 = lse3_(w2, w1 + thO[2].x, zE + thO[2].x);
        if (prodS | prodG) {
            int j = t - 30;
            emit(j,     make_float4(a1, b1, c1, 1.0f));
            emit(j + 1, make_float4(a2, b2, c2, 1.0f));
        }
        vM = a2; vX = b2; vY = c2;
        duM = nuM2; duX = nuX2; duY = nuY2;
    };

    // ---- superstep loop with global barrier ----
    for (int k = 0; k < KTOT; k++) {
        const int rel = k - k0;
        if (rel >= 0 && rel < NSUP) {
            const int T = rel * 16;
            if (rel == 0) { loadGroup(0, thA); loadGroup(4, thB); }

            if (T >= 32 && T <= 1520) {
                if (r == 0) loadBQ(T + 1);
                pairstep(T + 0,  thA[0], thA[1], bq[0], bq[1]);
                pairstep(T + 2,  thA[2], thA[3], bq[2], bq[3]);
                loadGroup(T + 8, thA);
                pairstep(T + 4,  thB[0], thB[1], bq[4], bq[5]);
                pairstep(T + 6,  thB[2], thB[3], bq[6], bq[7]);
                loadGroup(T + 12, thB);
                if (r == 0) loadBQ(T + 9);
                pairstep(T + 8,  thA[0], thA[1], bq[0], bq[1]);
                pairstep(T + 10, thA[2], thA[3], bq[2], bq[3]);
                loadGroup(T + 16, thA);
                pairstep(T + 12, thB[0], thB[1], bq[4], bq[5]);
                pairstep(T + 14, thB[2], thB[3], bq[6], bq[7]);
                loadGroup(T + 20, thB);
            } else {
                if (r == 0) loadBQ(T + 1);
                step(T + 0, thA[0], bq[0]);
                step(T + 1, thA[1], bq[1]);
                step(T + 2, thA[2], bq[2]);
                step(T + 3, thA[3], bq[3]);
                loadGroup(T + 8, thA);
                step(T + 4, thB[0], bq[4]);
                step(T + 5, thB[1], bq[5]);
                step(T + 6, thB[2], bq[6]);
                step(T + 7, thB[3], bq[7]);
                loadGroup(T + 12, thB);
                if (r == 0) loadBQ(T + 9);
                step(T + 8,  thA[0], bq[0]);
                step(T + 9,  thA[1], bq[1]);
                step(T + 10, thA[2], bq[2]);
                step(T + 11, thA[3], bq[3]);
                loadGroup(T + 16, thA);
                step(T + 12, thB[0], bq[4]);
                step(T + 13, thB[1], bq[5]);
                step(T + 14, thB[2], bq[6]);
                step(T + 15, thB[3], bq[7]);
                loadGroup(T + 20, thB);
            }
        }

        // ---- global sense barrier (release arrive, acquire poll) ----
        __syncthreads();
        if (tid == 0) {
            unsigned old;
            asm volatile("atom.acq_rel.gpu.global.add.u32 %0, [%1], 1;"
                         : "=r"(old) : "l"(&g_bar_count) : "memory");
            if (old % BLOCKS == BLOCKS - 1) {
                asm volatile("st.release.gpu.global.u32 [%0], %1;"
                             :: "l"(&g_bar_phase), "r"((unsigned)(k + 1)) : "memory");
            } else {
                unsigned ph = ld_acq_u(&g_bar_phase);
                while (ph < (unsigned)(k + 1)) {
                    nsleep(64);
                    ph = ld_acq_u(&g_bar_phase);
                }
            }
        }
        __syncthreads();
    }

    if (s == STRIPS - 1 && r == 31) {
        out[0] = LN2 * lse3_(vM, vX, vY);
    }
}

extern "C" void kernel_launch(void* const* d_in, const int* in_sizes, int n_in,
                              void* d_out, int out_size)
{
    const float* theta = (const float*)d_in[0];
    float* out = (float*)d_out;

    dim3 tgrid(STRIPS, TALLOC / TT, 32 / RG);
    hmm_transpose_kernel<<<tgrid, 256>>>(theta);
    hmm_init_kernel<<<1, 32>>>();
    hmm_fwd_kernel<<<BLOCKS, WPB * 32>>>(out);
}